// round 15
// baseline (speedup 1.0000x reference)
#include <cuda_runtime.h>
#include <cuda_fp16.h>
#include <cstdint>

#define C_DIM 272
#define T_DIM 1024
#define BATCH 128
#define NSUBJ 16
#define MT 64
#define NT 256
#define PIT 12                 // u32 per smem row (48B): conflict-free ldmatrix
#define AH_OFF 0
#define AL_OFF 768             // 64*PIT
#define BH_OFF 1536
#define BUF_U32 4608           // BH_OFF + 256*PIT
#define SMEM_BYTES (2 * BUF_U32 * 4)

__device__ int g_sidx[BATCH];
__device__ __half g_xh[(size_t)BATCH * T_DIM * C_DIM];      // x transposed [b][t][k]
__device__ __half g_Wh[(size_t)NSUBJ * C_DIM * C_DIM];      // W hi limb [s][c][k]
__device__ __half g_Wl[(size_t)NSUBJ * C_DIM * C_DIM];      // W lo limb

__global__ void decode_sidx_kernel(const int* __restrict__ raw) {
    __shared__ int is_i32;
    if (threadIdx.x == 0) is_i32 = 0;
    __syncthreads();
    int t = threadIdx.x;
    if (t < 64 && raw[2 * t + 1] != 0) atomicExch(&is_i32, 1);
    __syncthreads();
    if (t < BATCH) g_sidx[t] = is_i32 ? raw[t] : raw[2 * t];
}

// W -> fp16 limb split (hi + residual lo)
__global__ void wconv_kernel(const float* __restrict__ W) {
    const int i = blockIdx.x * blockDim.x + threadIdx.x;
    if (i < NSUBJ * C_DIM * C_DIM) {
        const float v = W[i];
        const __half h = __float2half_rn(v);
        g_Wh[i] = h;
        g_Wl[i] = __float2half_rn(v - __half2float(h));
    }
}

// x [b][c][t] -> xh [b][t][c] fp16 (32x32 smem transpose tiles)
__global__ void xconv_kernel(const float* __restrict__ x) {
    __shared__ float tile[32][33];
    const int b = blockIdx.z, t0 = blockIdx.x * 32, c0 = blockIdx.y * 32;
    const int tx = threadIdx.x, ty = threadIdx.y;
    const float* xb = x + (size_t)b * C_DIM * T_DIM;
#pragma unroll
    for (int i = 0; i < 4; i++) {
        const int c = c0 + ty + 8 * i;
        if (c < C_DIM) tile[ty + 8 * i][tx] = xb[(size_t)c * T_DIM + t0 + tx];
    }
    __syncthreads();
    __half* xh = g_xh + (size_t)b * T_DIM * C_DIM;
#pragma unroll
    for (int i = 0; i < 4; i++) {
        const int t = t0 + ty + 8 * i, c = c0 + tx;
        if (c < C_DIM) xh[(size_t)t * C_DIM + c] = __float2half_rn(tile[tx][ty + 8 * i]);
    }
}

__device__ __forceinline__ void mma16(float* d, const uint32_t* a, uint32_t b0, uint32_t b1) {
    asm volatile("mma.sync.aligned.m16n8k16.row.col.f32.f16.f16.f32 "
        "{%0,%1,%2,%3}, {%4,%5,%6,%7}, {%8,%9}, {%0,%1,%2,%3};"
        : "+f"(d[0]), "+f"(d[1]), "+f"(d[2]), "+f"(d[3])
        : "r"(a[0]), "r"(a[1]), "r"(a[2]), "r"(a[3]), "r"(b0), "r"(b1));
}
__device__ __forceinline__ void ldsm4(uint32_t* r, uint32_t addr) {
    asm volatile("ldmatrix.sync.aligned.m8n8.x4.shared.b16 {%0,%1,%2,%3}, [%4];"
        : "=r"(r[0]), "=r"(r[1]), "=r"(r[2]), "=r"(r[3]) : "r"(addr));
}
__device__ __forceinline__ uint32_t smem_u32p(const void* p) {
    uint32_t a;
    asm("{ .reg .u64 t; cvta.to.shared.u64 t, %1; cvt.u32.u64 %0, t; }" : "=r"(a) : "l"(p));
    return a;
}
__device__ __forceinline__ void cpa16(uint32_t dst, const void* src, uint32_t sz) {
    asm volatile("cp.async.cg.shared.global [%0], [%1], 16, %2;"
                 :: "r"(dst), "l"(src), "r"(sz) : "memory");
}

// CTA: 64(chan) x 256(time); 8 warps (2x4), warp tile 32x64.
// fp16 asymmetric x2 (A=Ah+Al, B=Bh), pre-converted inputs, cp.async staging.
__global__ __launch_bounds__(256, 2)
void mma_gemm_kernel(float* __restrict__ out) {
    extern __shared__ uint32_t sm[];
    const uint32_t smaddr = smem_u32p(sm);

    const int b = blockIdx.z, oBase = blockIdx.y * MT, tBase = blockIdx.x * NT;
    const int s = g_sidx[b];
    const __half* __restrict__ Wh = g_Wh + (size_t)s * C_DIM * C_DIM;
    const __half* __restrict__ Wl = g_Wl + (size_t)s * C_DIM * C_DIM;
    const __half* __restrict__ xh = g_xh + (size_t)b * T_DIM * C_DIM;

    const int tid = threadIdx.x, lane = tid & 31, warp = tid >> 5;
    const int wm = (warp >> 2) * 32, wn = (warp & 3) * 64;
    const int fr = lane >> 2, fc = lane & 3;

    // cp.async mappings
    const int aLimb = tid >> 7, aRow = (tid & 127) >> 1, aHalf = tid & 1;
    const bool aOK = (oBase + aRow) < C_DIM;
    const __half* aSrcBase = (aLimb ? Wl : Wh)
        + (size_t)(oBase + aRow) * C_DIM + aHalf * 8;            // + k0
    const uint32_t aDst = (uint32_t)((aLimb ? AL_OFF : AH_OFF)
        + aRow * PIT + aHalf * 4) * 4;                           // byte off in buf
    const uint32_t aSz = aOK ? 16u : 0u;

    const int bRow0 = tid >> 1, bHalf0 = tid & 1;                // chunk i=0
    const int bRow1 = (tid + 256) >> 1, bHalf1 = tid & 1;        // chunk i=1
    const __half* bSrc0 = xh + (size_t)(tBase + bRow0) * C_DIM + bHalf0 * 8;
    const __half* bSrc1 = xh + (size_t)(tBase + bRow1) * C_DIM + bHalf1 * 8;
    const uint32_t bDst0 = (uint32_t)(BH_OFF + bRow0 * PIT + bHalf0 * 4) * 4;
    const uint32_t bDst1 = (uint32_t)(BH_OFF + bRow1 * PIT + bHalf1 * 4) * 4;

    // ldmatrix per-lane byte offsets
    uint32_t aOffB[2];
#pragma unroll
    for (int mb = 0; mb < 2; mb++) {
        const int row = wm + mb * 16 + (lane & 7) + ((lane >> 3) & 1) * 8;
        aOffB[mb] = (uint32_t)(row * PIT + (lane >> 4) * 4) * 4;
    }
    uint32_t bOffB[4];
#pragma unroll
    for (int nbp = 0; nbp < 4; nbp++) {
        const int row = wn + nbp * 16 + (lane & 7) + ((lane >> 4) & 1) * 8;
        bOffB[nbp] = (uint32_t)(row * PIT + ((lane >> 3) & 1) * 4) * 4;
    }

    float acc[2][8][4];
#pragma unroll
    for (int mb = 0; mb < 2; mb++)
#pragma unroll
        for (int nb = 0; nb < 8; nb++)
#pragma unroll
            for (int j = 0; j < 4; j++) acc[mb][nb][j] = 0.0f;

    // prologue: async-fill buffer 0 with tile 0
    cpa16(smaddr + aDst, aSrcBase, aSz);
    cpa16(smaddr + bDst0, bSrc0, 16);
    cpa16(smaddr + bDst1, bSrc1, 16);
    asm volatile("cp.async.commit_group;" ::: "memory");
    asm volatile("cp.async.wait_group 0;" ::: "memory");
    __syncthreads();

    for (int ck = 0; ck < 17; ck++) {   // 272 = 17*16
        const uint32_t cb = smaddr + (uint32_t)(ck & 1) * (BUF_U32 * 4);

        // issue next tile's cp.async into the other buffer (overlaps mma)
        if (ck < 16) {
            const uint32_t nb = smaddr + (uint32_t)((ck + 1) & 1) * (BUF_U32 * 4);
            const int kn = (ck + 1) * 16;
            cpa16(nb + aDst, aSrcBase + kn, aSz);
            cpa16(nb + bDst0, bSrc0 + kn, 16);
            cpa16(nb + bDst1, bSrc1 + kn, 16);
            asm volatile("cp.async.commit_group;" ::: "memory");
        }

        // ---- A fragments (hi + lo limbs) ----
        uint32_t ah[2][4], al[2][4];
#pragma unroll
        for (int mb = 0; mb < 2; mb++) {
            ldsm4(ah[mb], cb + AH_OFF * 4 + aOffB[mb]);
            ldsm4(al[mb], cb + AL_OFF * 4 + aOffB[mb]);
        }
        // ---- B fragments + mma ----
#pragma unroll
        for (int nbq = 0; nbq < 2; nbq++) {
            uint32_t bh[2][4];
#pragma unroll
            for (int p = 0; p < 2; p++)
                ldsm4(bh[p], cb + BH_OFF * 4 + bOffB[nbq * 2 + p]);
#pragma unroll
            for (int p = 0; p < 2; p++)
#pragma unroll
                for (int i = 0; i < 2; i++) {
                    const int nb2 = nbq * 4 + p * 2 + i;
                    mma16(acc[0][nb2], ah[0], bh[p][2 * i], bh[p][2 * i + 1]);
                    mma16(acc[1][nb2], ah[1], bh[p][2 * i], bh[p][2 * i + 1]);
                }
#pragma unroll
            for (int p = 0; p < 2; p++)
#pragma unroll
                for (int i = 0; i < 2; i++) {
                    const int nb2 = nbq * 4 + p * 2 + i;
                    mma16(acc[0][nb2], al[0], bh[p][2 * i], bh[p][2 * i + 1]);
                    mma16(acc[1][nb2], al[1], bh[p][2 * i], bh[p][2 * i + 1]);
                }
        }

        if (ck < 16) {
            asm volatile("cp.async.wait_group 0;" ::: "memory");
            __syncthreads();
        }
    }

    float* __restrict__ ob = out + (size_t)b * C_DIM * T_DIM;
#pragma unroll
    for (int mb = 0; mb < 2; mb++) {
        const int r0 = oBase + wm + mb * 16 + fr;
        const int r1 = r0 + 8;
#pragma unroll
        for (int nb = 0; nb < 8; nb++) {
            const int cc = tBase + wn + nb * 8 + fc * 2;
            if (r0 < C_DIM)
                *(float2*)&ob[(size_t)r0 * T_DIM + cc] =
                    make_float2(acc[mb][nb][0], acc[mb][nb][1]);
            if (r1 < C_DIM)
                *(float2*)&ob[(size_t)r1 * T_DIM + cc] =
                    make_float2(acc[mb][nb][2], acc[mb][nb][3]);
        }
    }
}

extern "C" void kernel_launch(void* const* d_in, const int* in_sizes, int n_in,
                              void* d_out, int out_size) {
    const float* x = (const float*)d_in[0];
    const int* idx = (const int*)d_in[1];
    const float* W = (const float*)d_in[2];
    float* out = (float*)d_out;

    decode_sidx_kernel<<<1, 128>>>(idx);
    wconv_kernel<<<(NSUBJ * C_DIM * C_DIM + 255) / 256, 256>>>(W);
    dim3 xg(T_DIM / 32, (C_DIM + 31) / 32, BATCH);
    xconv_kernel<<<xg, dim3(32, 8)>>>(x);
    cudaFuncSetAttribute(mma_gemm_kernel,
                         cudaFuncAttributeMaxDynamicSharedMemorySize, SMEM_BYTES);
    dim3 grid(T_DIM / NT, (C_DIM + MT - 1) / MT, BATCH);   // (4, 5, 128)
    mma_gemm_kernel<<<grid, 256, SMEM_BYTES>>>(out);
}